// round 6
// baseline (speedup 1.0000x reference)
#include <cuda_runtime.h>
#include <math.h>

// Problem constants
#define NB 128   // batch
#define TS 512   // timesteps
#define DI 512   // input dim
#define HD 512   // hidden dim

// ---------------- packed f32x2 helpers (sm_100+ FFMA2 path) ----------------
__device__ __forceinline__ void fma2(unsigned long long& acc,
                                     unsigned long long a,
                                     unsigned long long b) {
    asm("fma.rn.f32x2 %0, %1, %2, %0;" : "+l"(acc) : "l"(a), "l"(b));
}

__device__ __forceinline__ void unpack2(unsigned long long v, float& lo, float& hi) {
    unsigned int a, b;
    asm("mov.b64 {%0, %1}, %2;" : "=r"(a), "=r"(b) : "l"(v));
    lo = __uint_as_float(a);
    hi = __uint_as_float(b);
}

#define CLUSTER_ARRIVE() asm volatile("barrier.cluster.arrive.aligned;" ::: "memory")
#define CLUSTER_WAIT()   asm volatile("barrier.cluster.wait.aligned;" ::: "memory")

// ---------------------------------------------------------------------------
// Kernel 1: xW = x @ Wx + b  (A:[65536,512] @ B:[512,512] -> C:[65536,512])
// (unchanged from R4 — passed with rel_err 3.7e-7)
// ---------------------------------------------------------------------------
__global__ __launch_bounds__(256) void xw_gemm(
    const float* __restrict__ A,
    const float* __restrict__ B,
    const float* __restrict__ bias,
    float* __restrict__ C)
{
    __shared__ float2 As2[128][16];   // [m][k], each entry = (a, a)
    __shared__ float  Bs[16][128];    // [k][n]

    const int m0  = blockIdx.y * 128;
    const int n0  = blockIdx.x * 128;
    const int tid = threadIdx.x;
    const int tn  = tid & 15;
    const int tm  = tid >> 4;

    unsigned long long acc[8][4];
#pragma unroll
    for (int i = 0; i < 8; i++)
#pragma unroll
        for (int j = 0; j < 4; j++) acc[i][j] = 0ULL;

    for (int k0 = 0; k0 < DI; k0 += 16) {
#pragma unroll
        for (int j = 0; j < 2; j++) {
            int f  = tid + j * 256;
            int m  = f >> 2;
            int kq = f & 3;
            float4 v = *(const float4*)(A + (size_t)(m0 + m) * DI + k0 + kq * 4);
            *(float4*)(&As2[m][kq * 4])     = make_float4(v.x, v.x, v.y, v.y);
            *(float4*)(&As2[m][kq * 4 + 2]) = make_float4(v.z, v.z, v.w, v.w);
        }
#pragma unroll
        for (int j = 0; j < 2; j++) {
            int f  = tid + j * 256;
            int k  = f >> 5;
            int nq = f & 31;
            *(float4*)(&Bs[k][nq * 4]) =
                *(const float4*)(B + (size_t)(k0 + k) * HD + n0 + nq * 4);
        }
        __syncthreads();

#pragma unroll
        for (int k = 0; k < 16; k++) {
            ulonglong2 b01 = *(const ulonglong2*)(&Bs[k][tn * 8]);
            ulonglong2 b23 = *(const ulonglong2*)(&Bs[k][tn * 8 + 4]);
#pragma unroll
            for (int i = 0; i < 8; i++) {
                unsigned long long a =
                    *(const unsigned long long*)(&As2[tm * 8 + i][k]);
                fma2(acc[i][0], a, b01.x);
                fma2(acc[i][1], a, b01.y);
                fma2(acc[i][2], a, b23.x);
                fma2(acc[i][3], a, b23.y);
            }
        }
        __syncthreads();
    }

    const float4 bb0 = *(const float4*)(bias + n0 + tn * 8);
    const float4 bb1 = *(const float4*)(bias + n0 + tn * 8 + 4);
#pragma unroll
    for (int i = 0; i < 8; i++) {
        float r0, r1, r2, r3, r4, r5, r6, r7;
        unpack2(acc[i][0], r0, r1);
        unpack2(acc[i][1], r2, r3);
        unpack2(acc[i][2], r4, r5);
        unpack2(acc[i][3], r6, r7);
        float* p = C + (size_t)(m0 + tm * 8 + i) * HD + n0 + tn * 8;
        *(float4*)p       = make_float4(r0 + bb0.x, r1 + bb0.y, r2 + bb0.z, r3 + bb0.w);
        *(float4*)(p + 4) = make_float4(r4 + bb1.x, r5 + bb1.y, r6 + bb1.z, r7 + bb1.w);
    }
}

// ---------------------------------------------------------------------------
// Kernel 2: persistent recurrence. ALL 512 timesteps in one launch.
//
// Grid: 16 clusters (y) x 8 CTAs/cluster (x) = 128 blocks, 128 threads each.
// Cluster y owns batch rows [8y, 8y+8); CTA x within the cluster owns hidden
// cols [64x, 64x+64). The dependency closure of a row-group is exactly its
// 8-CTA cluster, so barrier.cluster (HW, ~400cyc) replaces per-step kernel
// launches, and the 16 clusters run fully decoupled.
//
// Wh slice [512][64] (128KB) lives in smem for the whole kernel.
// h_{t-1} rows (8x512) are staged per step as duplicated float2 (33KB) so the
// inner loop is LDS.64 + LDS.128 + 2xFFMA2 per k = issue/smem floor.
// ---------------------------------------------------------------------------
#define HP 514                       // padded Hs row (float2): 4112B -> rows on distinct banks
#define SMEM_WS_BYTES (512 * 64 * 4)               // 131072
#define SMEM_RNN_BYTES (SMEM_WS_BYTES + 8 * HP * 8) // +32896 = 163968

__global__ __launch_bounds__(128, 1) __cluster_dims__(8, 1, 1)
void rnn_persistent(const float* __restrict__ Wh,
                    const float* __restrict__ h0,
                    float* __restrict__ out)
{
    extern __shared__ char smem[];
    float*  Ws = (float*)smem;                         // [512][64]
    float2* Hs = (float2*)(smem + SMEM_WS_BYTES);      // [8][HP] duplicated

    const int tid = threadIdx.x;
    const int m0  = blockIdx.y * 8;    // batch-row base
    const int n0  = blockIdx.x * 64;   // hidden-col base

    // ---- load Wh slice once: 512x64 floats = 8192 float4, 64 per thread ----
#pragma unroll 8
    for (int j = 0; j < 64; j++) {
        int f  = tid + j * 128;
        int k  = f >> 4;
        int nq = f & 15;
        *(float4*)(Ws + k * 64 + nq * 4) =
            *(const float4*)(Wh + (size_t)k * HD + n0 + nq * 4);
    }

    // compute-thread mapping: warp = n-quarter, lane&7 = row, lane>>3 = col grp
    const int lane = tid & 31;
    const int wrp  = tid >> 5;
    const int r    = lane & 7;                 // 0..7   (row in tile)
    const int c    = wrp * 16 + (lane >> 3) * 4;  // 0..63 (col in tile)

    // staging mapping: 16 threads per row, 8 float4 each
    const int srow = tid >> 4;                 // 0..7
    const int sq   = tid & 15;

    const float2* hrow = Hs + r * HP;
    const float*  wcol = Ws + c;

    for (int t = 0; t < TS; t++) {
        // ---- stage h_{t-1} rows into smem (duplicated pairs) ----
        const float* src = (t == 0)
            ? (h0 + (size_t)(m0 + srow) * HD)
            : (out + ((size_t)(m0 + srow) * TS + (t - 1)) * HD);
        float2* drow = Hs + srow * HP;
#pragma unroll
        for (int j = 0; j < 8; j++) {
            int q = sq + j * 16;
            float4 v = *(const float4*)(src + q * 4);
            *(float4*)(drow + q * 4)     = make_float4(v.x, v.x, v.y, v.y);
            *(float4*)(drow + q * 4 + 2) = make_float4(v.z, v.z, v.w, v.w);
        }

        // prefetch xw_t for this thread's 4 outputs (independent of Hs)
        float* pio = out + ((size_t)(m0 + r) * TS + t) * HD + n0 + c;
        float4 xw = *(const float4*)pio;

        __syncthreads();

        // ---- h_{t-1} @ Wh : 4 outputs/thread, even/odd k chains ----
        unsigned long long a0 = 0ULL, a1 = 0ULL, b0 = 0ULL, b1 = 0ULL;
#pragma unroll 8
        for (int k = 0; k < HD; k += 2) {
            unsigned long long h0v = *(const unsigned long long*)(hrow + k);
            ulonglong2 w0 = *(const ulonglong2*)(wcol + (size_t)k * 64);
            fma2(a0, h0v, w0.x);
            fma2(a1, h0v, w0.y);
            unsigned long long h1v = *(const unsigned long long*)(hrow + k + 1);
            ulonglong2 w1 = *(const ulonglong2*)(wcol + (size_t)(k + 1) * 64);
            fma2(b0, h1v, w1.x);
            fma2(b1, h1v, w1.y);
        }

        float e0, e1, e2, e3, o0, o1, o2, o3;
        unpack2(a0, e0, e1);
        unpack2(a1, e2, e3);
        unpack2(b0, o0, o1);
        unpack2(b1, o2, o3);

        float4 hv;
        hv.x = tanhf(xw.x + e0 + o0);
        hv.y = tanhf(xw.y + e1 + o1);
        hv.z = tanhf(xw.z + e2 + o2);
        hv.w = tanhf(xw.w + e3 + o3);
        *(float4*)pio = hv;

        // ---- cluster-wide step barrier (also a full block barrier) ----
        __threadfence();
        CLUSTER_ARRIVE();
        CLUSTER_WAIT();
    }
}

// ---------------------------------------------------------------------------
// Launch: xW into d_out, then ONE persistent kernel for all 512 steps.
// ---------------------------------------------------------------------------
extern "C" void kernel_launch(void* const* d_in, const int* in_sizes, int n_in,
                              void* d_out, int out_size) {
    (void)in_sizes; (void)n_in; (void)out_size;
    const float* x  = (const float*)d_in[0];   // [128, 512, 512]
    const float* h0 = (const float*)d_in[1];   // [128, 512]
    const float* Wx = (const float*)d_in[2];   // [512, 512]
    const float* Wh = (const float*)d_in[3];   // [512, 512]
    const float* b  = (const float*)d_in[4];   // [512]
    float* out = (float*)d_out;                // [128, 512, 512]

    dim3 gx(HD / 128, (NB * TS) / 128);        // (4, 512)
    xw_gemm<<<gx, 256>>>(x, Wx, b, out);

    static int smem_set = 0;
    if (!smem_set) {
        cudaFuncSetAttribute(rnn_persistent,
                             cudaFuncAttributeMaxDynamicSharedMemorySize,
                             SMEM_RNN_BYTES);
        smem_set = 1;
    }
    dim3 gs(8, NB / 8);                        // 8 CTAs/cluster x 16 clusters
    rnn_persistent<<<gs, 128, SMEM_RNN_BYTES>>>(Wh, h0, out);
}